// round 1
// baseline (speedup 1.0000x reference)
#include <cuda_runtime.h>
#include <math.h>

#define NPIX (512*512)
#define NB 16
#define SIG 0.125f
#define TAUC 0.125f
#define ALPHA_C 0.15f
#define MU_C 10.0f
#define EPS_C 1e-6f
#define INV1T (1.0f/1.125f)
#define FRLO 0.43000000000029104f
#define FRHI 0.5699999999953434f

// ---------------- device scratch (no runtime allocation allowed) ----------------
__device__ float g_tmpR[NB*NPIX];
__device__ float g_tmpM[NB*NPIX];
__device__ float g_x  [NB*NPIX];
__device__ float g_Nh [NB*NPIX];
__device__ float g_gm [NB*NPIX];
__device__ float g_Wx [NB*NPIX];
__device__ float g_Wy [NB*NPIX];
__device__ float g_u [2][NB*NPIX];
__device__ float g_ub[2][NB*NPIX];
__device__ float g_px[2][NB*NPIX];
__device__ float g_py[2][NB*NPIX];

__device__ unsigned g_hist1[NB*256];
__device__ unsigned g_histT[64*256];
__device__ unsigned g_tprefix[64];
__device__ unsigned g_trank[64];
__device__ float    g_selval[64];
__device__ float    g_lo[NB];
__device__ float    g_ihl[NB];   // 1/(hi-lo+eps)
__device__ float    g_isig[NB];  // 1/sigma

__constant__ int c_ranksX[4] = {2621, 2622, 259521, 259522};
__constant__ int c_ranksG[2] = {131071, 131072};

// ---------------- horizontal 31-max-pool on R and max(G,B) ----------------
__global__ void k_hpool(const float* __restrict__ Iy) {
    int row = blockIdx.x, b = blockIdx.y;
    __shared__ float sR[512];
    __shared__ float sM[512];
    int j = threadIdx.x;
    const float* base = Iy + (size_t)b*3*NPIX + (size_t)row*512;
    float r = __ldg(base + j);
    float m = fmaxf(__ldg(base + NPIX + j), __ldg(base + 2*NPIX + j));
    sR[j] = r; sM[j] = m;
    __syncthreads();
    float mr = r, mm = m;
    #pragma unroll
    for (int t = -15; t <= 15; t++) {
        int jj = j + t; jj = jj < 0 ? 0 : (jj > 511 ? 511 : jj);
        mr = fmaxf(mr, sR[jj]);
        mm = fmaxf(mm, sM[jj]);
    }
    size_t o = (size_t)b*NPIX + (size_t)row*512 + j;
    g_tmpR[o] = mr; g_tmpM[o] = mm;
}

// ---------------- vertical 31-max-pool + x = |Rmax-GBmax| + R ----------------
__global__ void k_vpool_x(const float* __restrict__ Iy) {
    int b = blockIdx.z;
    int col0 = blockIdx.x * 32;
    int row0 = blockIdx.y * 64;
    __shared__ float sR[94][32];
    __shared__ float sM[94][32];
    int tid = threadIdx.y * 32 + threadIdx.x;
    for (int idx = tid; idx < 94*32; idx += 256) {
        int rr = idx >> 5, cc = idx & 31;
        int gr = row0 + rr - 15; gr = gr < 0 ? 0 : (gr > 511 ? 511 : gr);
        size_t o = (size_t)b*NPIX + (size_t)gr*512 + col0 + cc;
        sR[rr][cc] = g_tmpR[o];
        sM[rr][cc] = g_tmpM[o];
    }
    __syncthreads();
    int tx = threadIdx.x;
    for (int k = 0; k < 8; k++) {
        int r = threadIdx.y * 8 + k;
        float mr = -1e30f, mm = -1e30f;
        #pragma unroll
        for (int t = 0; t < 31; t++) {
            mr = fmaxf(mr, sR[r+t][tx]);
            mm = fmaxf(mm, sM[r+t][tx]);
        }
        int gr = row0 + r;
        size_t o = (size_t)b*NPIX + (size_t)gr*512 + col0 + tx;
        float R = __ldg(Iy + (size_t)b*3*NPIX + (size_t)gr*512 + col0 + tx);
        g_x[o] = fabsf(mr - mm) + R;
    }
}

// ---------------- radix-select machinery (exact order statistics) ----------------
__global__ void k_zero_hists() {
    int i = blockIdx.x * blockDim.x + threadIdx.x;
    if (i < NB*256) g_hist1[i] = 0;
    for (int k = i; k < 64*256; k += gridDim.x * blockDim.x) g_histT[k] = 0;
}

__global__ void k_hist1(int which) {
    const float* src = which ? g_gm : g_x;
    int b = blockIdx.y;
    __shared__ unsigned h[8*256];
    for (int i = threadIdx.x; i < 8*256; i += blockDim.x) h[i] = 0;
    __syncthreads();
    unsigned rep = (threadIdx.x & 7) * 256;
    const float* p = src + (size_t)b*NPIX;
    for (int i = blockIdx.x * blockDim.x + threadIdx.x; i < NPIX; i += gridDim.x * blockDim.x) {
        unsigned v = __float_as_uint(__ldg(p + i));
        atomicAdd(&h[rep + (v >> 24)], 1u);
    }
    __syncthreads();
    for (int i = threadIdx.x; i < 256; i += blockDim.x) {
        unsigned s = 0;
        #pragma unroll
        for (int r = 0; r < 8; r++) s += h[r*256 + i];
        if (s) atomicAdd(&g_hist1[b*256 + i], s);
    }
}

__global__ void k_histT(int which, int perB, int pass) {
    const float* src = which ? g_gm : g_x;
    int t = blockIdx.y;
    int b = t / perB;
    int shift = 8 * (4 - pass);
    unsigned mask = 0xFFFFFFFFu << (shift + 8);
    unsigned prefix = g_tprefix[t];
    __shared__ unsigned h[8*256];
    for (int i = threadIdx.x; i < 8*256; i += blockDim.x) h[i] = 0;
    __syncthreads();
    unsigned rep = (threadIdx.x & 7) * 256;
    const float* p = src + (size_t)b*NPIX;
    for (int i = blockIdx.x * blockDim.x + threadIdx.x; i < NPIX; i += gridDim.x * blockDim.x) {
        unsigned v = __float_as_uint(__ldg(p + i));
        if ((v & mask) == prefix) atomicAdd(&h[rep + ((v >> shift) & 0xFF)], 1u);
    }
    __syncthreads();
    for (int i = threadIdx.x; i < 256; i += blockDim.x) {
        unsigned s = 0;
        #pragma unroll
        for (int r = 0; r < 8; r++) s += h[r*256 + i];
        if (s) atomicAdd(&g_histT[t*256 + i], s);
    }
}

__global__ void k_resolve(int nT, int perB, int pass, int which) {
    int t = threadIdx.x;
    if (t < nT) {
        int b = t / perB;
        const unsigned* hist = (pass == 1) ? &g_hist1[b*256] : &g_histT[t*256];
        unsigned rank, prefix;
        if (pass == 1) {
            rank = (unsigned)(which ? c_ranksG[t % perB] : c_ranksX[t % perB]);
            prefix = 0u;
        } else {
            rank = g_trank[t]; prefix = g_tprefix[t];
        }
        unsigned cum = 0; int bkt = 255;
        for (int i = 0; i < 256; i++) {
            unsigned c = hist[i];
            if (cum + c > rank) { bkt = i; break; }
            cum += c;
        }
        rank -= cum;
        int shift = 8 * (4 - pass);
        prefix |= ((unsigned)bkt) << shift;
        if (pass == 4) g_selval[t] = __uint_as_float(prefix);
        else { g_tprefix[t] = prefix; g_trank[t] = rank; }
    }
    __syncthreads();
    for (int i = threadIdx.x; i < 64*256; i += blockDim.x) g_histT[i] = 0;
    if (pass == 4) for (int i = threadIdx.x; i < NB*256; i += blockDim.x) g_hist1[i] = 0;
}

__global__ void k_fin_x() {
    int b = threadIdx.x;
    if (b < NB) {
        float lo = g_selval[b*4+0]*(1.0f-FRLO) + g_selval[b*4+1]*FRLO;
        float hi = g_selval[b*4+2]*(1.0f-FRHI) + g_selval[b*4+3]*FRHI;
        g_lo[b] = lo;
        g_ihl[b] = 1.0f / (hi - lo + EPS_C);
    }
}

__global__ void k_fin_gm() {
    int b = threadIdx.x;
    if (b < NB) {
        float med = 0.5f * (g_selval[b*2+0] + g_selval[b*2+1]);
        float sig = fmaxf(med, EPS_C);
        g_isig[b] = 1.0f / sig;
    }
}

// ---------------- N_hat + grad magnitude ----------------
__global__ void k_nhat() {
    int b = blockIdx.z;
    int j = blockIdx.x * 32 + threadIdx.x;
    int i = blockIdx.y * 8 + threadIdx.y;
    size_t base = (size_t)b*NPIX;
    float lo = g_lo[b], inv = g_ihl[b];
    size_t o = base + (size_t)i*512 + j;
    float xc = __ldg(&g_x[o]);
    float n00 = fminf(fmaxf((xc - lo) * inv, 0.0f), 1.0f);
    float dx = 0.0f, dy = 0.0f;
    if (j < 511) {
        float xr = __ldg(&g_x[o + 1]);
        dx = fminf(fmaxf((xr - lo) * inv, 0.0f), 1.0f) - n00;
    }
    if (i < 511) {
        float xd = __ldg(&g_x[o + 512]);
        dy = fminf(fmaxf((xd - lo) * inv, 0.0f), 1.0f) - n00;
    }
    g_Nh[o] = n00;
    g_gm[o] = sqrtf(dx*dx + dy*dy + EPS_C);
}

// ---------------- Wx, Wy ----------------
__global__ void k_wxy() {
    int b = blockIdx.z;
    int j = blockIdx.x * 32 + threadIdx.x;
    int i = blockIdx.y * 8 + threadIdx.y;
    size_t base = (size_t)b*NPIX;
    float isig = g_isig[b];
    size_t o = base + (size_t)i*512 + j;
    float n00 = __ldg(&g_Nh[o]);
    float dx = (j < 511) ? (__ldg(&g_Nh[o + 1]) - n00) : 0.0f;
    float dy = (i < 511) ? (__ldg(&g_Nh[o + 512]) - n00) : 0.0f;
    g_Wx[o] = 1.0f + MU_C * expf(-fabsf(dx) * isig);
    g_Wy[o] = 1.0f + MU_C * expf(-fabsf(dy) * isig);
}

// ---------------- fused primal-dual step ----------------
// Each thread recomputes the neighbor's new px/py (pure function of old state),
// so dual update + divergence + primal update fuse into one launch.
template<bool FIRST, bool LAST>
__global__ void k_pd(int rd, int wr, float* __restrict__ out) {
    int b = blockIdx.z;
    int j = blockIdx.x * 32 + threadIdx.x;
    int i = blockIdx.y * 8 + threadIdx.y;
    size_t base = (size_t)b*NPIX;
    size_t o = base + (size_t)i*512 + j;

    const float* __restrict__ ub = FIRST ? g_Nh : g_ub[rd];
    float nh  = __ldg(&g_Nh[o]);
    float ubc = FIRST ? nh : __ldg(&ub[o]);

    float dxc = (j < 511) ? (__ldg(&ub[o + 1])   - ubc) : 0.0f;
    float dyc = (i < 511) ? (__ldg(&ub[o + 512]) - ubc) : 0.0f;

    float bx = ALPHA_C * __ldg(&g_Wx[o]);
    float by = ALPHA_C * __ldg(&g_Wy[o]);
    float px0 = FIRST ? 0.0f : __ldg(&g_px[rd][o]);
    float py0 = FIRST ? 0.0f : __ldg(&g_py[rd][o]);
    float pxn = fminf(fmaxf(px0 + SIG*dxc, -bx), bx);
    float pyn = fminf(fmaxf(py0 + SIG*dyc, -by), by);

    float pxl = 0.0f, pyu = 0.0f;
    if (j > 0) {
        float ubl = __ldg(&ub[o - 1]);
        float bxl = ALPHA_C * __ldg(&g_Wx[o - 1]);
        float pl  = FIRST ? 0.0f : __ldg(&g_px[rd][o - 1]);
        pxl = fminf(fmaxf(pl + SIG*(ubc - ubl), -bxl), bxl);
    }
    if (i > 0) {
        float ubu = __ldg(&ub[o - 512]);
        float byu = ALPHA_C * __ldg(&g_Wy[o - 512]);
        float pu  = FIRST ? 0.0f : __ldg(&g_py[rd][o - 512]);
        pyu = fminf(fmaxf(pu + SIG*(ubc - ubu), -byu), byu);
    }

    float uc = FIRST ? ubc : __ldg(&g_u[rd][o]);
    float un = (uc + TAUC*(pxn - pxl + pyn - pyu) + TAUC*nh) * INV1T;

    if (LAST) {
        out[o] = fminf(fmaxf(un, 0.0f), 1.0f);
    } else {
        g_u [wr][o] = un;
        g_ub[wr][o] = 2.0f*un - uc;
        g_px[wr][o] = pxn;
        g_py[wr][o] = pyn;
    }
}

// ---------------- launch ----------------
extern "C" void kernel_launch(void* const* d_in, const int* in_sizes, int n_in,
                              void* d_out, int out_size) {
    const float* Iy = (const float*)d_in[0];
    float* out = (float*)d_out;

    dim3 b32x8(32, 8);
    dim3 gFull(16, 64, NB);

    k_hpool  <<<dim3(512, NB), 512>>>(Iy);
    k_vpool_x<<<dim3(16, 8, NB), b32x8>>>(Iy);

    k_zero_hists<<<16, 256>>>();

    // quantiles of x (p01, p99): ranks k and k+1 for linear interpolation
    k_hist1<<<dim3(16, NB), 256>>>(0);
    k_resolve<<<1, 256>>>(64, 4, 1, 0);
    for (int pass = 2; pass <= 4; pass++) {
        k_histT<<<dim3(8, 64), 256>>>(0, 4, pass);
        k_resolve<<<1, 256>>>(64, 4, pass, 0);
    }
    k_fin_x<<<1, 32>>>();

    k_nhat<<<gFull, b32x8>>>();

    // median of grad magnitude
    k_hist1<<<dim3(16, NB), 256>>>(1);
    k_resolve<<<1, 256>>>(32, 2, 1, 1);
    for (int pass = 2; pass <= 4; pass++) {
        k_histT<<<dim3(8, 32), 256>>>(1, 2, pass);
        k_resolve<<<1, 256>>>(32, 2, pass, 1);
    }
    k_fin_gm<<<1, 32>>>();

    k_wxy<<<gFull, b32x8>>>();

    // 30 primal-dual iterations, ping-pong state
    k_pd<true, false><<<gFull, b32x8>>>(0, 0, nullptr);
    for (int t = 1; t < 29; t++)
        k_pd<false, false><<<gFull, b32x8>>>((t - 1) & 1, t & 1, nullptr);
    k_pd<false, true><<<gFull, b32x8>>>(0, 0, out);
}